// round 15
// baseline (speedup 1.0000x reference)
#include <cuda_runtime.h>
#include <cuda_bf16.h>

#define BB 8
#define NN 2048
#define CC 128
#define KK 512

typedef unsigned long long ull;
typedef unsigned int uint;

// ---------------- device scratch (no allocations allowed) ----------------
__device__ float g_s1[BB * NN];
__device__ float g_s2[BB * NN];
__device__ uint  g_maxs2i[BB];              // int-encoded max of s2 per batch
__device__ float g_hp[BB * CC];
__device__ float g_xpart[512 * CC];
__device__ int   g_rank[BB * NN];
__device__ int   g_sel[BB * KK];            // slot = rank (any bijection works)
__device__ __align__(16) ull g_Wp[64 * CC]; // (W[2k][c], W[2k+1][c]) pairs
// split-bf16 h for the tensor GEMM (row-major [b][j][c])
__device__ __align__(16) __nv_bfloat16 g_hhi[(long)BB * NN * CC];
__device__ __align__(16) __nv_bfloat16 g_hlo[(long)BB * NN * CC];
// K-split partials
__device__ __align__(16) float g_part[2L * BB * KK * CC];   // 16.8 MB
__device__ float g_zp[2 * BB * KK];

__device__ __forceinline__ float lrelu(float v) { return fmaxf(v, 0.01f * v); }

__device__ __forceinline__ uint fkey(float f) {
    uint u = __float_as_uint(f);
    return (u & 0x80000000u) ? ~u : (u | 0x80000000u);
}
__device__ __forceinline__ float fdec(uint k) {
    uint u = (k & 0x80000000u) ? (k & 0x7FFFFFFFu) : ~k;
    return __uint_as_float(u);
}

// packed bf16x2 convert: result = {lo=a, hi=b}
__device__ __forceinline__ uint cvt2(float a, float b) {
    uint r;
    asm("cvt.rn.bf16x2.f32 %0, %1, %2;" : "=r"(r) : "f"(b), "f"(a));
    return r;
}

__device__ __forceinline__ float ex2f(float x) {
    float r;
    asm("ex2.approx.f32 %0, %1;" : "=f"(r) : "f"(x));
    return r;
}

// ---------------------------------------------------------------------------
// k_wp: pre-pair W rows; block 0 also zero-inits g_maxs2i.
// ---------------------------------------------------------------------------
__global__ void __launch_bounds__(256) k_wp(const float* __restrict__ W) {
    int idx = blockIdx.x * 256 + threadIdx.x;
    if (blockIdx.x == 0 && threadIdx.x < BB) g_maxs2i[threadIdx.x] = 0u;
    int k2 = idx >> 7, c = idx & 127;
    float w0 = W[(2 * k2) * CC + c];
    float w1 = W[(2 * k2 + 1) * CC + c];
    ull p;
    asm("mov.b64 %0, {%1, %2};" : "=l"(p) : "f"(w0), "f"(w1));
    g_Wp[idx] = p;
}

// ---------------------------------------------------------------------------
// k_h (fused): h = x@W -> split bf16; s1/s2; s2 max; x col partials.
// ---------------------------------------------------------------------------
__global__ void __launch_bounds__(128) k_h(const float* __restrict__ x,
                                           const float* __restrict__ a) {
    __shared__ __align__(16) float xs[32][128];
    __shared__ uint wmax[4];
    int t = threadIdx.x;
    int g = t >> 5, lane = t & 31;
    long row0 = (long)blockIdx.x * 32;
    int b = blockIdx.x >> 6;

    const float4* xsrc = (const float4*)(x + row0 * CC);
    float4* xdst = (float4*)xs;
#pragma unroll
    for (int q = 0; q < 8; q++) xdst[t + 128 * q] = xsrc[t + 128 * q];
    __syncthreads();

    ull acc[8][4];
#pragma unroll
    for (int r = 0; r < 8; r++)
#pragma unroll
        for (int c = 0; c < 4; c++) acc[r][c] = 0;

    const ulonglong2* Wp2 = (const ulonglong2*)g_Wp;

#pragma unroll 4
    for (int k2 = 0; k2 < 64; k2++) {
        ulonglong2 wa = Wp2[k2 * 64 + 2 * lane];
        ulonglong2 wb = Wp2[k2 * 64 + 2 * lane + 1];
#pragma unroll
        for (int r = 0; r < 8; r++) {
            ull xv = *(const ull*)&xs[g * 8 + r][2 * k2];
            asm("fma.rn.f32x2 %0, %1, %2, %0;" : "+l"(acc[r][0]) : "l"(xv), "l"(wa.x));
            asm("fma.rn.f32x2 %0, %1, %2, %0;" : "+l"(acc[r][1]) : "l"(xv), "l"(wa.y));
            asm("fma.rn.f32x2 %0, %1, %2, %0;" : "+l"(acc[r][2]) : "l"(xv), "l"(wb.x));
            asm("fma.rn.f32x2 %0, %1, %2, %0;" : "+l"(acc[r][3]) : "l"(xv), "l"(wb.y));
        }
    }

    float4 a1v = ((const float4*)a)[lane];
    float4 a2v = ((const float4*)(a + CC))[lane];
    float s2max = -3.4e38f;

#pragma unroll
    for (int r = 0; r < 8; r++) {
        long row = row0 + g * 8 + r;
        float v[4];
#pragma unroll
        for (int c = 0; c < 4; c++) {
            float lo, hi;
            asm("mov.b64 {%0, %1}, %2;" : "=f"(lo), "=f"(hi) : "l"(acc[r][c]));
            v[c] = lo + hi;
        }

        uint hp01 = cvt2(v[0], v[1]);
        uint hp23 = cvt2(v[2], v[3]);
        float f0 = __uint_as_float(hp01 << 16), f1 = __uint_as_float(hp01 & 0xffff0000u);
        float f2 = __uint_as_float(hp23 << 16), f3 = __uint_as_float(hp23 & 0xffff0000u);
        uint lp01 = cvt2(v[0] - f0, v[1] - f1);
        uint lp23 = cvt2(v[2] - f2, v[3] - f3);
        uint2 hv; hv.x = hp01; hv.y = hp23;
        uint2 lv; lv.x = lp01; lv.y = lp23;
        *(uint2*)&g_hhi[row * CC + 4 * lane] = hv;
        *(uint2*)&g_hlo[row * CC + 4 * lane] = lv;

        float p1 = v[0] * a1v.x + v[1] * a1v.y + v[2] * a1v.z + v[3] * a1v.w;
        float p2 = v[0] * a2v.x + v[1] * a2v.y + v[2] * a2v.z + v[3] * a2v.w;
#pragma unroll
        for (int o = 16; o; o >>= 1) {
            p1 += __shfl_xor_sync(0xffffffffu, p1, o);
            p2 += __shfl_xor_sync(0xffffffffu, p2, o);
        }
        s2max = fmaxf(s2max, p2);
        if (lane == 0) { g_s1[row] = p1; g_s2[row] = p2; }
    }

    if (lane == 0) wmax[g] = fkey(s2max);

    float s = 0.f;
#pragma unroll 8
    for (int r = 0; r < 32; r++) s += xs[r][t];
    g_xpart[blockIdx.x * CC + t] = s;

    __syncthreads();
    if (t == 0) {
        uint m = max(max(wmax[0], wmax[1]), max(wmax[2], wmax[3]));
        atomicMax(&g_maxs2i[b], m);
    }
}

// ---------------------------------------------------------------------------
// k_rank: full rank + scatter + hp in one launch.
// ---------------------------------------------------------------------------
__global__ void __launch_bounds__(256) k_rank(const float* __restrict__ W) {
    int b = blockIdx.y;
    int t = threadIdx.x;

    if (blockIdx.x == 32) {
        __shared__ float xm[128];
        __shared__ float part[256];
        int c = t & 127, half = t >> 7;
        float s = 0.f;
#pragma unroll 8
        for (int k = half * 32; k < half * 32 + 32; k++)
            s += g_xpart[(b * 64 + k) * CC + c];
        part[t] = s;
        __syncthreads();
        if (half == 0) xm[c] = (part[c] + part[c + 128]) * (1.0f / NN);
        __syncthreads();
        float acc = 0.f;
#pragma unroll 8
        for (int k = half * 64; k < half * 64 + 64; k++)
            acc = fmaf(xm[k], W[k * CC + c], acc);
        part[t] = acc;
        __syncthreads();
        if (half == 0) g_hp[b * CC + c] = fmaxf(part[c] + part[c + 128], 0.f);
        return;
    }

    __shared__ ull keys[NN];          // 16 KB
    __shared__ int part[256];
    for (int q = t; q < NN; q += 256)
        keys[q] = ((ull)fkey(g_s1[b * NN + q]) << 11) | (unsigned)(NN - 1 - q);
    __syncthreads();

    int il = t & 63, jq = t >> 6;
    int i = blockIdx.x * 64 + il;
    ull me = keys[i];
    int cnt = 0;
    int j0 = jq * 512;
#pragma unroll 8
    for (int j = 0; j < 512; j++)
        cnt += (keys[j0 + j] > me) ? 1 : 0;
    part[t] = cnt;
    __syncthreads();
    if (jq == 0) {
        int rank = part[il] + part[il + 64] + part[il + 128] + part[il + 192];
        g_rank[b * NN + i] = rank;
        if (rank < KK) g_sel[b * KK + rank] = i;
    }
}

// ---------------------------------------------------------------------------
// k_gemm: D_partial = P @ h over ONE K-half, P computed INLINE.
// Tile 64M x 64N, 512 thr (16 warps, 4m x 4n), 2-stage pipeline, 2 barriers
// per chunk. grid (16 mn, 2 ksplit, 8 b) = 256 blocks -> 2 blocks/SM.
// Writes raw fp32 partial + partial Z; fill done by ks==0 blocks.
// ---------------------------------------------------------------------------
#define PITCH 72
#define ARR (64 * PITCH)
#define STG_ELEMS (4 * ARR)                       // Ahi,Alo,Bhi,Blo per stage
#define GEMM_SMEM (2 * STG_ELEMS * 2 + 4096 + 256 + 256)
#define L2E 1.44269504f

__device__ __forceinline__ void mma_bf16(float* d, const uint* a, const uint* bfr) {
    asm("mma.sync.aligned.m16n8k16.row.col.f32.bf16.bf16.f32 "
        "{%0,%1,%2,%3}, {%4,%5,%6,%7}, {%8,%9}, {%0,%1,%2,%3};"
        : "+f"(d[0]), "+f"(d[1]), "+f"(d[2]), "+f"(d[3])
        : "r"(a[0]), "r"(a[1]), "r"(a[2]), "r"(a[3]), "r"(bfr[0]), "r"(bfr[1]));
}

__device__ __forceinline__ void ldsm4(uint* r, uint addr) {
    asm volatile("ldmatrix.sync.aligned.m8n8.x4.shared.b16 {%0,%1,%2,%3}, [%4];"
                 : "=r"(r[0]), "=r"(r[1]), "=r"(r[2]), "=r"(r[3]) : "r"(addr));
}
__device__ __forceinline__ void ldsm4t(uint* r, uint addr) {
    asm volatile("ldmatrix.sync.aligned.m8n8.x4.trans.shared.b16 {%0,%1,%2,%3}, [%4];"
                 : "=r"(r[0]), "=r"(r[1]), "=r"(r[2]), "=r"(r[3]) : "r"(addr));
}

__global__ void __launch_bounds__(512) k_gemm(float* __restrict__ out) {
    extern __shared__ __align__(16) char SM[];
    __nv_bfloat16* S = (__nv_bfloat16*)SM;                       // 2-stage tiles
    float* s2s = (float*)(SM + 2 * STG_ELEMS * 2);               // 4096 B (this K-half)
    float* s1s = (float*)(SM + 2 * STG_ELEMS * 2 + 4096);        // 256 B
    float* zs  = (float*)(SM + 2 * STG_ELEMS * 2 + 4352);        // 256 B

    int t = threadIdx.x, warp = t >> 5, lane = t & 31;
    int wm = warp >> 2, wn = warp & 3;   // 4m x 4n warp grid
    int mt = blockIdx.x & 7, nt = blockIdx.x >> 3;
    int ks = blockIdx.y, b = blockIdx.z;

    const __nv_bfloat16* srcB[2] = {
        g_hhi + (long)b * NN * CC + (long)ks * 1024 * CC + nt * 64,
        g_hlo + (long)b * NN * CC + (long)ks * 1024 * CC + nt * 64
    };

#define COPY_B(buf, chunk)                                                        \
    {                                                                             \
        _Pragma("unroll")                                                         \
        for (int arr = 0; arr < 2; arr++) {                                       \
            const __nv_bfloat16* sp = srcB[arr] + (long)(chunk) * 64 * CC;        \
            uint dbase = (uint)__cvta_generic_to_shared(                          \
                S + (buf) * STG_ELEMS + (2 + arr) * ARR);                         \
            int row = t >> 3, seg = t & 7;                                        \
            asm volatile("cp.async.cg.shared.global [%0], [%1], 16;"              \
                         :: "r"(dbase + (row * PITCH + seg * 8) * 2),             \
                            "l"(sp + (long)row * CC + seg * 8) : "memory");       \
        }                                                                         \
        asm volatile("cp.async.commit_group;" ::: "memory");                      \
    }

    // inline P: slot = t>>3 (64 slots), q = t&7, col = 2(q&3) + 8p + 32(q>>2)
#define COMPUTE_A(buf, chunk)                                                     \
    {                                                                             \
        const float* s2c = s2s + (chunk) * 64;                                    \
        __nv_bfloat16* Ah = S + (buf) * STG_ELEMS + slot * PITCH;                 \
        __nv_bfloat16* Al = Ah + ARR;                                             \
        _Pragma("unroll")                                                         \
        for (int p = 0; p < 4; p++) {                                             \
            int col = colbase + 8 * p;                                            \
            float2 sv = *(const float2*)(s2c + col);                              \
            float e0 = lrelu(s1v + sv.x);                                         \
            float e1 = lrelu(s1v + sv.y);                                         \
            float w0 = ex2f(fmaf(e0, L2E, nML2E));                                \
            float w1 = ex2f(fmaf(e1, L2E, nML2E));                                \
            zacc += w0 + w1;                                                      \
            uint hp = cvt2(w0, w1);                                               \
            float f0 = __uint_as_float(hp << 16);                                 \
            float f1 = __uint_as_float(hp & 0xffff0000u);                         \
            uint lp = cvt2(w0 - f0, w1 - f1);                                     \
            *(uint*)(Ah + col) = hp;                                              \
            *(uint*)(Al + col) = lp;                                              \
        }                                                                         \
    }

    float acc[2][4];
#pragma unroll
    for (int fn = 0; fn < 2; fn++)
#pragma unroll
        for (int z = 0; z < 4; z++) acc[fn][z] = 0.f;

    COPY_B(0, 0)

    // preload this K-half's s2 (1024 floats) + per-slot s1
    {
        if (t < 256) {
            const float4* s2src = (const float4*)(g_s2 + (long)b * NN + ks * 1024);
            ((float4*)s2s)[t] = s2src[t];
        }
        if (t < 64) {
            int sel = g_sel[b * KK + mt * 64 + t];
            s1s[t] = g_s1[b * NN + sel];
        }
    }

    // fused fill (ks==0 only): unselected rows i in [mt*256,+256)
    if (ks == 0) {
        int i = mt * 256 + (t & 255);
        int half = t >> 8;
        if (g_rank[b * NN + i] >= KK) {
            float* ob = out + (long)b * CC * NN + i;
            const float* hpb = g_hp + b * CC + nt * 64 + half * 32;
#pragma unroll 8
            for (int c = 0; c < 32; c++)
                ob[(long)(nt * 64 + half * 32 + c) * NN] = hpb[c];
        }
    }
    __syncthreads();

    int slot = t >> 3, q = t & 7;
    int colbase = 2 * (q & 3) + 32 * (q >> 2);
    float s1v = s1s[slot];
    float ms2 = fdec(g_maxs2i[b]);
    float M = lrelu(s1v + ms2);
    float nML2E = -M * L2E;
    float zacc = 0.f;

    COMPUTE_A(0, 0)

    int lg = lane & 15, lh = lane >> 4;

    for (int c = 0; c < 16; c++) {
        if (c + 1 < 16) {
            COPY_B((c + 1) & 1, c + 1)
            COMPUTE_A((c + 1) & 1, c + 1)
            asm volatile("cp.async.wait_group 1;" ::: "memory");
        } else {
            asm volatile("cp.async.wait_group 0;" ::: "memory");
        }
        __syncthreads();   // B(c) + A(c) visible

        uint Sb = (uint)__cvta_generic_to_shared(S + (c & 1) * STG_ELEMS);
        uint sAhi = Sb, sAlo = Sb + ARR * 2, sBhi = Sb + 2 * ARR * 2, sBlo = Sb + 3 * ARR * 2;

#pragma unroll
        for (int kq = 0; kq < 4; kq++) {
            int k0 = kq * 16;
            uint ahi[4], alo[4], bhi[4], blo[4];
            uint ra = (uint)((wm * 16 + lg) * PITCH + k0 + lh * 8) * 2;
            ldsm4(ahi, sAhi + ra);
            ldsm4(alo, sAlo + ra);
            uint rb = (uint)((k0 + lg) * PITCH + wn * 16 + lh * 8) * 2;
            ldsm4t(bhi, sBhi + rb);
            ldsm4t(blo, sBlo + rb);

#pragma unroll
            for (int fn = 0; fn < 2; fn++) {
                mma_bf16(acc[fn], ahi, bhi + 2 * fn);
                mma_bf16(acc[fn], ahi, blo + 2 * fn);
                mma_bf16(acc[fn], alo, bhi + 2 * fn);
            }
        }
        __syncthreads();   // protect buf c from next iteration's writes
    }
#undef COPY_B
#undef COMPUTE_A

    // partial Z (this K-half), 8-lane slot reduction; identical across nt.
    zacc += __shfl_xor_sync(0xffffffffu, zacc, 1);
    zacc += __shfl_xor_sync(0xffffffffu, zacc, 2);
    zacc += __shfl_xor_sync(0xffffffffu, zacc, 4);
    if (q == 0) zs[slot] = zacc;
    __syncthreads();
    if (t < 64) g_zp[(ks * BB + b) * KK + mt * 64 + t] = zs[t];

    // raw partial store
    int g2 = lane >> 2, tig = lane & 3;
    float* pb = g_part + (((long)ks * BB + b) * KK + mt * 64) * CC;
    {
        int zslot = wm * 16 + g2;
#pragma unroll
        for (int fn = 0; fn < 2; fn++) {
            int c0 = nt * 64 + wn * 16 + fn * 8 + 2 * tig;
            pb[(long)zslot * CC + c0]           = acc[fn][0];
            pb[(long)zslot * CC + c0 + 1]       = acc[fn][1];
            pb[(long)(zslot + 8) * CC + c0]     = acc[fn][2];
            pb[(long)(zslot + 8) * CC + c0 + 1] = acc[fn][3];
        }
    }
}

// ---------------------------------------------------------------------------
// k_comb: deterministic fixed-order combine of the two K-half partials.
// grid (16, B), 256 thr: block handles 32 slots x 128 cols.
// ---------------------------------------------------------------------------
__global__ void __launch_bounds__(256) k_comb(float* __restrict__ out) {
    int b = blockIdx.y, t = threadIdx.x;
    int slot = blockIdx.x * 32 + (t >> 3);
    int cb = (t & 7) * 16;
    long pidx = ((long)b * KK + slot) * CC + cb;
    const float4* p0 = (const float4*)(g_part + pidx);
    const float4* p1 = (const float4*)(g_part + (long)BB * KK * CC + pidx);
    float z = 1.f / (g_zp[b * KK + slot] + g_zp[BB * KK + b * KK + slot]);
    int i = g_sel[b * KK + slot];
    float* ob = out + (long)b * CC * NN + i;
#pragma unroll
    for (int u = 0; u < 4; u++) {
        float4 a = p0[u], c4 = p1[u];
        ob[(long)(cb + 4 * u + 0) * NN] = fmaxf((a.x + c4.x) * z, 0.f);
        ob[(long)(cb + 4 * u + 1) * NN] = fmaxf((a.y + c4.y) * z, 0.f);
        ob[(long)(cb + 4 * u + 2) * NN] = fmaxf((a.z + c4.z) * z, 0.f);
        ob[(long)(cb + 4 * u + 3) * NN] = fmaxf((a.w + c4.w) * z, 0.f);
    }
}

// ---------------------------------------------------------------------------
extern "C" void kernel_launch(void* const* d_in, const int* in_sizes, int n_in,
                              void* d_out, int out_size) {
    const float* x = nullptr;
    const float* W = nullptr;
    const float* a = nullptr;
    for (int k = 0; k < n_in; k++) {
        if (in_sizes[k] == BB * NN * CC)      x = (const float*)d_in[k];
        else if (in_sizes[k] == CC * CC)      W = (const float*)d_in[k];
        else if (in_sizes[k] == 2 * CC)       a = (const float*)d_in[k];
    }
    float* out = (float*)d_out;

    static int smem_set = 0;
    if (!smem_set) {
        cudaFuncSetAttribute(k_gemm, cudaFuncAttributeMaxDynamicSharedMemorySize, GEMM_SMEM);
        smem_set = 1;
    }

    k_wp   <<<32, 256>>>(W);
    k_h    <<<BB * NN / 32, 128>>>(x, a);
    k_rank <<<dim3(33, BB), 256>>>(W);
    k_gemm <<<dim3(16, 2, BB), 512, GEMM_SMEM>>>(out);
    k_comb <<<dim3(16, BB), 256>>>(out);
}

// round 16
// speedup vs baseline: 1.0843x; 1.0843x over previous
#include <cuda_runtime.h>
#include <cuda_bf16.h>

#define BB 8
#define NN 2048
#define CC 128
#define KK 512

typedef unsigned long long ull;
typedef unsigned int uint;

// ---------------- device scratch (no allocations allowed) ----------------
__device__ float g_s1[BB * NN];
__device__ float g_s2[BB * NN];
__device__ uint  g_maxs2i[BB];              // int-encoded max of s2 per batch
__device__ float g_hp[BB * CC];
__device__ float g_xpart[512 * CC];
__device__ int   g_rank[BB * NN];
__device__ int   g_sel[BB * KK];            // slot = rank (any bijection works)
__device__ __align__(16) ull g_Wp[64 * CC]; // (W[2k][c], W[2k+1][c]) pairs
// split-bf16 h for the tensor GEMM (row-major [b][j][c])
__device__ __align__(16) __nv_bfloat16 g_hhi[(long)BB * NN * CC];
__device__ __align__(16) __nv_bfloat16 g_hlo[(long)BB * NN * CC];
// K-split partials (4 quarters)
__device__ __align__(16) float g_part[4L * BB * KK * CC];   // 33.6 MB
__device__ float g_zp[4 * BB * KK];

__device__ __forceinline__ float lrelu(float v) { return fmaxf(v, 0.01f * v); }

__device__ __forceinline__ uint fkey(float f) {
    uint u = __float_as_uint(f);
    return (u & 0x80000000u) ? ~u : (u | 0x80000000u);
}
__device__ __forceinline__ float fdec(uint k) {
    uint u = (k & 0x80000000u) ? (k & 0x7FFFFFFFu) : ~k;
    return __uint_as_float(u);
}

// packed bf16x2 convert: result = {lo=a, hi=b}
__device__ __forceinline__ uint cvt2(float a, float b) {
    uint r;
    asm("cvt.rn.bf16x2.f32 %0, %1, %2;" : "=r"(r) : "f"(b), "f"(a));
    return r;
}

__device__ __forceinline__ float ex2f(float x) {
    float r;
    asm("ex2.approx.f32 %0, %1;" : "=f"(r) : "f"(x));
    return r;
}

// ---------------------------------------------------------------------------
// k_wp: pre-pair W rows; block 0 also zero-inits g_maxs2i.
// ---------------------------------------------------------------------------
__global__ void __launch_bounds__(256) k_wp(const float* __restrict__ W) {
    int idx = blockIdx.x * 256 + threadIdx.x;
    if (blockIdx.x == 0 && threadIdx.x < BB) g_maxs2i[threadIdx.x] = 0u;
    int k2 = idx >> 7, c = idx & 127;
    float w0 = W[(2 * k2) * CC + c];
    float w1 = W[(2 * k2 + 1) * CC + c];
    ull p;
    asm("mov.b64 %0, {%1, %2};" : "=l"(p) : "f"(w0), "f"(w1));
    g_Wp[idx] = p;
}

// ---------------------------------------------------------------------------
// k_h (fused): h = x@W -> split bf16; s1/s2; s2 max; x col partials.
// ---------------------------------------------------------------------------
__global__ void __launch_bounds__(128) k_h(const float* __restrict__ x,
                                           const float* __restrict__ a) {
    __shared__ __align__(16) float xs[32][128];
    __shared__ uint wmax[4];
    int t = threadIdx.x;
    int g = t >> 5, lane = t & 31;
    long row0 = (long)blockIdx.x * 32;
    int b = blockIdx.x >> 6;

    const float4* xsrc = (const float4*)(x + row0 * CC);
    float4* xdst = (float4*)xs;
#pragma unroll
    for (int q = 0; q < 8; q++) xdst[t + 128 * q] = xsrc[t + 128 * q];
    __syncthreads();

    ull acc[8][4];
#pragma unroll
    for (int r = 0; r < 8; r++)
#pragma unroll
        for (int c = 0; c < 4; c++) acc[r][c] = 0;

    const ulonglong2* Wp2 = (const ulonglong2*)g_Wp;

#pragma unroll 4
    for (int k2 = 0; k2 < 64; k2++) {
        ulonglong2 wa = Wp2[k2 * 64 + 2 * lane];
        ulonglong2 wb = Wp2[k2 * 64 + 2 * lane + 1];
#pragma unroll
        for (int r = 0; r < 8; r++) {
            ull xv = *(const ull*)&xs[g * 8 + r][2 * k2];
            asm("fma.rn.f32x2 %0, %1, %2, %0;" : "+l"(acc[r][0]) : "l"(xv), "l"(wa.x));
            asm("fma.rn.f32x2 %0, %1, %2, %0;" : "+l"(acc[r][1]) : "l"(xv), "l"(wa.y));
            asm("fma.rn.f32x2 %0, %1, %2, %0;" : "+l"(acc[r][2]) : "l"(xv), "l"(wb.x));
            asm("fma.rn.f32x2 %0, %1, %2, %0;" : "+l"(acc[r][3]) : "l"(xv), "l"(wb.y));
        }
    }

    float4 a1v = ((const float4*)a)[lane];
    float4 a2v = ((const float4*)(a + CC))[lane];
    float s2max = -3.4e38f;

#pragma unroll
    for (int r = 0; r < 8; r++) {
        long row = row0 + g * 8 + r;
        float v[4];
#pragma unroll
        for (int c = 0; c < 4; c++) {
            float lo, hi;
            asm("mov.b64 {%0, %1}, %2;" : "=f"(lo), "=f"(hi) : "l"(acc[r][c]));
            v[c] = lo + hi;
        }

        uint hp01 = cvt2(v[0], v[1]);
        uint hp23 = cvt2(v[2], v[3]);
        float f0 = __uint_as_float(hp01 << 16), f1 = __uint_as_float(hp01 & 0xffff0000u);
        float f2 = __uint_as_float(hp23 << 16), f3 = __uint_as_float(hp23 & 0xffff0000u);
        uint lp01 = cvt2(v[0] - f0, v[1] - f1);
        uint lp23 = cvt2(v[2] - f2, v[3] - f3);
        uint2 hv; hv.x = hp01; hv.y = hp23;
        uint2 lv; lv.x = lp01; lv.y = lp23;
        *(uint2*)&g_hhi[row * CC + 4 * lane] = hv;
        *(uint2*)&g_hlo[row * CC + 4 * lane] = lv;

        float p1 = v[0] * a1v.x + v[1] * a1v.y + v[2] * a1v.z + v[3] * a1v.w;
        float p2 = v[0] * a2v.x + v[1] * a2v.y + v[2] * a2v.z + v[3] * a2v.w;
#pragma unroll
        for (int o = 16; o; o >>= 1) {
            p1 += __shfl_xor_sync(0xffffffffu, p1, o);
            p2 += __shfl_xor_sync(0xffffffffu, p2, o);
        }
        s2max = fmaxf(s2max, p2);
        if (lane == 0) { g_s1[row] = p1; g_s2[row] = p2; }
    }

    if (lane == 0) wmax[g] = fkey(s2max);

    float s = 0.f;
#pragma unroll 8
    for (int r = 0; r < 32; r++) s += xs[r][t];
    g_xpart[blockIdx.x * CC + t] = s;

    __syncthreads();
    if (t == 0) {
        uint m = max(max(wmax[0], wmax[1]), max(wmax[2], wmax[3]));
        atomicMax(&g_maxs2i[b], m);
    }
}

// ---------------------------------------------------------------------------
// k_rank: full rank + scatter + hp in one launch.
// ---------------------------------------------------------------------------
__global__ void __launch_bounds__(256) k_rank(const float* __restrict__ W) {
    int b = blockIdx.y;
    int t = threadIdx.x;

    if (blockIdx.x == 32) {
        __shared__ float xm[128];
        __shared__ float part[256];
        int c = t & 127, half = t >> 7;
        float s = 0.f;
#pragma unroll 8
        for (int k = half * 32; k < half * 32 + 32; k++)
            s += g_xpart[(b * 64 + k) * CC + c];
        part[t] = s;
        __syncthreads();
        if (half == 0) xm[c] = (part[c] + part[c + 128]) * (1.0f / NN);
        __syncthreads();
        float acc = 0.f;
#pragma unroll 8
        for (int k = half * 64; k < half * 64 + 64; k++)
            acc = fmaf(xm[k], W[k * CC + c], acc);
        part[t] = acc;
        __syncthreads();
        if (half == 0) g_hp[b * CC + c] = fmaxf(part[c] + part[c + 128], 0.f);
        return;
    }

    __shared__ ull keys[NN];          // 16 KB
    __shared__ int part[256];
    for (int q = t; q < NN; q += 256)
        keys[q] = ((ull)fkey(g_s1[b * NN + q]) << 11) | (unsigned)(NN - 1 - q);
    __syncthreads();

    int il = t & 63, jq = t >> 6;
    int i = blockIdx.x * 64 + il;
    ull me = keys[i];
    int cnt = 0;
    int j0 = jq * 512;
#pragma unroll 8
    for (int j = 0; j < 512; j++)
        cnt += (keys[j0 + j] > me) ? 1 : 0;
    part[t] = cnt;
    __syncthreads();
    if (jq == 0) {
        int rank = part[il] + part[il + 64] + part[il + 128] + part[il + 192];
        g_rank[b * NN + i] = rank;
        if (rank < KK) g_sel[b * KK + rank] = i;
    }
}

// ---------------------------------------------------------------------------
// k_gemm: D_partial = P @ h over ONE K-quarter (512 j), P computed INLINE
// and ONCE (nt=1: block tile 64M x 128N -> no exp duplication).
// 512 thr = 16 warps (4m x 4n) of 16M x 32N. Chunk 32 j, 4-stage cp.async
// pipeline, single barrier per chunk. grid (8 mt, 4 ks, 8 b) = 256 blocks,
// 110.5 KB smem -> 2 blocks/SM. Writes fp32 partial + partial Z.
// ---------------------------------------------------------------------------
#define APITCH 40
#define BPITCH 136
#define A_ELEMS (64 * APITCH)                 // 2560
#define B_ELEMS (32 * BPITCH)                 // 4352
#define STG_ELEMS (2 * A_ELEMS + 2 * B_ELEMS) // 13824 elems, 27648 B
#define OFF_ALO A_ELEMS
#define OFF_BHI (2 * A_ELEMS)
#define OFF_BLO (2 * A_ELEMS + B_ELEMS)
#define NSTG 4
#define GEMM_SMEM (NSTG * STG_ELEMS * 2 + 2048 + 256 + 256)
#define L2E 1.44269504f

__device__ __forceinline__ void mma_bf16(float* d, const uint* a, const uint* bfr) {
    asm("mma.sync.aligned.m16n8k16.row.col.f32.bf16.bf16.f32 "
        "{%0,%1,%2,%3}, {%4,%5,%6,%7}, {%8,%9}, {%0,%1,%2,%3};"
        : "+f"(d[0]), "+f"(d[1]), "+f"(d[2]), "+f"(d[3])
        : "r"(a[0]), "r"(a[1]), "r"(a[2]), "r"(a[3]), "r"(bfr[0]), "r"(bfr[1]));
}

__device__ __forceinline__ void ldsm4(uint* r, uint addr) {
    asm volatile("ldmatrix.sync.aligned.m8n8.x4.shared.b16 {%0,%1,%2,%3}, [%4];"
                 : "=r"(r[0]), "=r"(r[1]), "=r"(r[2]), "=r"(r[3]) : "r"(addr));
}
__device__ __forceinline__ void ldsm4t(uint* r, uint addr) {
    asm volatile("ldmatrix.sync.aligned.m8n8.x4.trans.shared.b16 {%0,%1,%2,%3}, [%4];"
                 : "=r"(r[0]), "=r"(r[1]), "=r"(r[2]), "=r"(r[3]) : "r"(addr));
}

__global__ void __launch_bounds__(512) k_gemm(float* __restrict__ out) {
    extern __shared__ __align__(16) char SM[];
    __nv_bfloat16* S = (__nv_bfloat16*)SM;                       // 4-stage tiles
    float* s2s = (float*)(SM + NSTG * STG_ELEMS * 2);            // 2048 B (K-quarter)
    float* s1s = (float*)(SM + NSTG * STG_ELEMS * 2 + 2048);     // 256 B
    float* zs  = (float*)(SM + NSTG * STG_ELEMS * 2 + 2304);     // 256 B

    int t = threadIdx.x, warp = t >> 5, lane = t & 31;
    int wm = warp >> 2, wn = warp & 3;   // 4m x 4n warp grid (16M x 32N tiles)
    int mt = blockIdx.x;
    int ks = blockIdx.y, b = blockIdx.z;

    const __nv_bfloat16* srcB[2] = {
        g_hhi + ((long)b * NN + ks * 512) * CC,
        g_hlo + ((long)b * NN + ks * 512) * CC
    };

    // B chunk: 32 j x 128 c; one 16B cp.async per thread per array
#define COPY_B(buf, chunk)                                                        \
    {                                                                             \
        _Pragma("unroll")                                                         \
        for (int arr = 0; arr < 2; arr++) {                                       \
            const __nv_bfloat16* sp = srcB[arr] + (long)(chunk) * 32 * CC;        \
            uint dbase = (uint)__cvta_generic_to_shared(                          \
                S + (buf) * STG_ELEMS + OFF_BHI + arr * B_ELEMS);                 \
            int row = t >> 4, seg = t & 15;                                       \
            asm volatile("cp.async.cg.shared.global [%0], [%1], 16;"              \
                         :: "r"(dbase + (row * BPITCH + seg * 8) * 2),            \
                            "l"(sp + (long)row * CC + seg * 8) : "memory");       \
        }                                                                         \
        asm volatile("cp.async.commit_group;" ::: "memory");                      \
    }

    // inline P: slot = t>>3 (64 slots), q = t&7, cols = 2q + 16p (p=0..1)
#define COMPUTE_A(buf, chunk)                                                     \
    {                                                                             \
        const float* s2c = s2s + (chunk) * 32;                                    \
        __nv_bfloat16* Ah = S + (buf) * STG_ELEMS + slot * APITCH;                \
        __nv_bfloat16* Al = Ah + OFF_ALO;                                         \
        _Pragma("unroll")                                                         \
        for (int p = 0; p < 2; p++) {                                             \
            int col = 2 * q + 16 * p;                                             \
            float2 sv = *(const float2*)(s2c + col);                              \
            float e0 = lrelu(s1v + sv.x);                                         \
            float e1 = lrelu(s1v + sv.y);                                         \
            float w0 = ex2f(fmaf(e0, L2E, nML2E));                                \
            float w1 = ex2f(fmaf(e1, L2E, nML2E));                                \
            zacc += w0 + w1;                                                      \
            uint hp = cvt2(w0, w1);                                               \
            float f0 = __uint_as_float(hp << 16);                                 \
            float f1 = __uint_as_float(hp & 0xffff0000u);                         \
            uint lp = cvt2(w0 - f0, w1 - f1);                                     \
            *(uint*)(Ah + col) = hp;                                              \
            *(uint*)(Al + col) = lp;                                              \
        }                                                                         \
    }

    float acc[4][4];
#pragma unroll
    for (int fn = 0; fn < 4; fn++)
#pragma unroll
        for (int z = 0; z < 4; z++) acc[fn][z] = 0.f;

    COPY_B(0, 0)
    COPY_B(1, 1)

    // preload this K-quarter's s2 (512 floats) + per-slot s1
    {
        if (t < 128) {
            const float4* s2src = (const float4*)(g_s2 + (long)b * NN + ks * 512);
            ((float4*)s2s)[t] = s2src[t];
        }
        if (t < 64) {
            int sel = g_sel[b * KK + mt * 64 + t];
            s1s[t] = g_s1[b * NN + sel];
        }
    }

    // fused fill (ks==0 only): unselected rows i in [mt*256,+256), all 128 c
    if (ks == 0) {
        int i = mt * 256 + (t & 255);
        int half = t >> 8;
        if (g_rank[b * NN + i] >= KK) {
            float* ob = out + (long)b * CC * NN + i;
            const float* hpb = g_hp + b * CC + half * 64;
#pragma unroll 8
            for (int c = 0; c < 64; c++)
                ob[(long)(half * 64 + c) * NN] = hpb[c];
        }
    }
    __syncthreads();

    int slot = t >> 3, q = t & 7;
    float s1v = s1s[slot];
    float ms2 = fdec(g_maxs2i[b]);
    float M = lrelu(s1v + ms2);
    float nML2E = -M * L2E;
    float zacc = 0.f;

    COMPUTE_A(0, 0)

    int lg = lane & 15, lh = lane >> 4;

    for (int c = 0; c < 16; c++) {
        if (c + 1 < 16) COMPUTE_A((c + 1) & 3, c + 1)
        if (c + 2 < 16) COPY_B((c + 2) & 3, c + 2)

        if (c < 14) {
            asm volatile("cp.async.wait_group 2;" ::: "memory");
        } else if (c == 14) {
            asm volatile("cp.async.wait_group 1;" ::: "memory");
        } else {
            asm volatile("cp.async.wait_group 0;" ::: "memory");
        }
        __syncthreads();   // single barrier: B(c) waits + A(c) STS visible

        uint Sb = (uint)__cvta_generic_to_shared(S + (c & 3) * STG_ELEMS);
        uint sAhi = Sb, sAlo = Sb + OFF_ALO * 2;
        uint sBhi = Sb + OFF_BHI * 2, sBlo = Sb + OFF_BLO * 2;

#pragma unroll
        for (int kq = 0; kq < 2; kq++) {
            int k0 = kq * 16;
            uint ahi[4], alo[4], bhi[8], blo[8];
            uint ra = (uint)((wm * 16 + lg) * APITCH + k0 + lh * 8) * 2;
            ldsm4(ahi, sAhi + ra);
            ldsm4(alo, sAlo + ra);
            uint rb0 = (uint)((k0 + lg) * BPITCH + wn * 32 + lh * 8) * 2;
            uint rb1 = (uint)((k0 + lg) * BPITCH + wn * 32 + 16 + lh * 8) * 2;
            ldsm4t(bhi,     sBhi + rb0);
            ldsm4t(bhi + 4, sBhi + rb1);
            ldsm4t(blo,     sBlo + rb0);
            ldsm4t(blo + 4, sBlo + rb1);

#pragma unroll
            for (int fn = 0; fn < 4; fn++) {
                mma_bf16(acc[fn], ahi, bhi + 2 * fn);
                mma_bf16(acc[fn], ahi, blo + 2 * fn);
                mma_bf16(acc[fn], alo, bhi + 2 * fn);
            }
        }
    }
#undef COPY_B
#undef COMPUTE_A

    __syncthreads();
    // partial Z (this K-quarter), 8-lane slot reduction.
    zacc += __shfl_xor_sync(0xffffffffu, zacc, 1);
    zacc += __shfl_xor_sync(0xffffffffu, zacc, 2);
    zacc += __shfl_xor_sync(0xffffffffu, zacc, 4);
    if (q == 0) zs[slot] = zacc;
    __syncthreads();
    if (t < 64) g_zp[(ks * BB + b) * KK + mt * 64 + t] = zs[t];

    // raw partial store [slot][c]
    int g2 = lane >> 2, tig = lane & 3;
    float* pb = g_part + (((long)ks * BB + b) * KK + mt * 64) * CC;
    {
        int zslot = wm * 16 + g2;
#pragma unroll
        for (int fn = 0; fn < 4; fn++) {
            int c0 = wn * 32 + fn * 8 + 2 * tig;
            pb[(long)zslot * CC + c0]           = acc[fn][0];
            pb[(long)zslot * CC + c0 + 1]       = acc[fn][1];
            pb[(long)(zslot + 8) * CC + c0]     = acc[fn][2];
            pb[(long)(zslot + 8) * CC + c0 + 1] = acc[fn][3];
        }
    }
}

// ---------------------------------------------------------------------------
// k_comb: deterministic fixed-order combine of the four K-quarter partials.
// grid (16, B), 256 thr: block handles 32 slots x 128 cols.
// ---------------------------------------------------------------------------
__global__ void __launch_bounds__(256) k_comb(float* __restrict__ out) {
    int b = blockIdx.y, t = threadIdx.x;
    int slot = blockIdx.x * 32 + (t >> 3);
    int cb = (t & 7) * 16;
    long pidx = ((long)b * KK + slot) * CC + cb;
    const long POFF = (long)BB * KK * CC;
    const float4* p0 = (const float4*)(g_part + pidx);
    const float4* p1 = (const float4*)(g_part + POFF + pidx);
    const float4* p2 = (const float4*)(g_part + 2 * POFF + pidx);
    const float4* p3 = (const float4*)(g_part + 3 * POFF + pidx);
    float z = 1.f / (((g_zp[b * KK + slot] + g_zp[BB * KK + b * KK + slot])
                    + g_zp[2 * BB * KK + b * KK + slot]) + g_zp[3 * BB * KK + b * KK + slot]);
    int i = g_sel[b * KK + slot];
    float* ob = out + (long)b * CC * NN + i;
#pragma unroll
    for (int u = 0; u < 4; u++) {
        float4 a = p0[u], c1 = p1[u], c2 = p2[u], c3 = p3[u];
        ob[(long)(cb + 4 * u + 0) * NN] = fmaxf((((a.x + c1.x) + c2.x) + c3.x) * z, 0.f);
        ob[(long)(cb + 4 * u + 1) * NN] = fmaxf((((a.y + c1.y) + c2.y) + c3.y) * z, 0.f);
        ob[(long)(cb + 4 * u + 2) * NN] = fmaxf((((a.z + c1.z) + c2.z) + c3.z) * z, 0.f);
        ob[(long)(cb + 4 * u + 3) * NN] = fmaxf((((a.w + c1.w) + c2.w) + c3.w) * z, 0.f);
    }
}

// ---------------------------------------------------------------------------
extern "C" void kernel_launch(void* const* d_in, const int* in_sizes, int n_in,
                              void* d_out, int out_size) {
    const float* x = nullptr;
    const float* W = nullptr;
    const float* a = nullptr;
    for (int k = 0; k < n_in; k++) {
        if (in_sizes[k] == BB * NN * CC)      x = (const float*)d_in[k];
        else if (in_sizes[k] == CC * CC)      W = (const float*)d_in[k];
        else if (in_sizes[k] == 2 * CC)       a = (const float*)d_in[k];
    }
    float* out = (float*)d_out;

    static int smem_set = 0;
    if (!smem_set) {
        cudaFuncSetAttribute(k_gemm, cudaFuncAttributeMaxDynamicSharedMemorySize, GEMM_SMEM);
        smem_set = 1;
    }

    k_wp   <<<32, 256>>>(W);
    k_h    <<<BB * NN / 32, 128>>>(x, a);
    k_rank <<<dim3(33, BB), 256>>>(W);
    k_gemm <<<dim3(8, 4, BB), 512, GEMM_SMEM>>>(out);
    k_comb <<<dim3(16, BB), 256>>>(out);
}